// round 2
// baseline (speedup 1.0000x reference)
#include <cuda_runtime.h>
#include <math.h>

#define Bz   4
#define Lz   2048
#define Dz   192
#define DIz  384
#define DSz  64
#define DCz  4
#define DRz  12
#define BLz  (Bz*Lz)        // 8192
#define E2z  (2*DIz)        // 768
#define XDBz (DRz+DSz)      // 76

// ---- scratch (no allocations allowed; __device__ globals) ----
__device__ float g_h  [BLz*Dz];     // layernormed hidden
__device__ float g_xz [BLz*E2z];    // in-proj output (x | z)
__device__ float g_x  [BLz*DIz];    // post conv+silu
__device__ float g_xdb[BLz*XDBz];   // x-proj output (dt_in | B)
__device__ float g_dt [BLz*DIz];    // softplus dt
__device__ float g_dtu[BLz*DIz];    // dt * u
__device__ float g_y  [BLz*DIz];    // gated scan output

__device__ __forceinline__ float warp_sum(float v) {
#pragma unroll
    for (int o = 16; o; o >>= 1) v += __shfl_xor_sync(0xffffffffu, v, o);
    return v;
}

// ============================================================================
// Kernel 1: residual = residual + hidden ; LayerNorm -> g_h ; residual -> out[1]
// one warp per row (D=192 = 6 x 32)
// ============================================================================
__global__ __launch_bounds__(256) void k_ln(
    const float* __restrict__ hs, const float* __restrict__ res,
    const float* __restrict__ lw, const float* __restrict__ lb,
    float* __restrict__ out_res)
{
    int warp = (blockIdx.x * blockDim.x + threadIdx.x) >> 5;
    int lane = threadIdx.x & 31;
    if (warp >= BLz) return;
    const float* ph = hs + (size_t)warp * Dz;
    const float* pr = res + (size_t)warp * Dz;
    float v[6];
    float s = 0.f;
#pragma unroll
    for (int j = 0; j < 6; j++) {
        int e = lane + j * 32;
        v[j] = ph[e] + pr[e];
        s += v[j];
    }
    s = warp_sum(s);
    float mu = s * (1.0f / Dz);
    float q = 0.f;
#pragma unroll
    for (int j = 0; j < 6; j++) { float d = v[j] - mu; q += d * d; }
    q = warp_sum(q);
    float rstd = rsqrtf(q * (1.0f / Dz) + 1e-5f);
    float* po = out_res + (size_t)warp * Dz;
    float* phh = g_h + (size_t)warp * Dz;
#pragma unroll
    for (int j = 0; j < 6; j++) {
        int e = lane + j * 32;
        po[e] = v[j];
        phh[e] = (v[j] - mu) * rstd * lw[e] + lb[e];
    }
}

// ============================================================================
// Generic GEMM body: C[M,N] = A[M,K] * W[N,K]^T   (both row-major)
// 64x64 tile, K-chunk 16, 256 threads, 4x4 micro-tile. M multiple of 64,
// K multiple of 16 (and of 4 for float4 loads); N guarded.
// ============================================================================
__device__ __forceinline__ void gemm_body(
    const float* __restrict__ A, const float* __restrict__ W,
    float* __restrict__ C, int N, int K)
{
    __shared__ float As[16][64];
    __shared__ float Bs[16][64];
    int tid = threadIdx.x;
    int tc = tid & 15, tr = tid >> 4;
    int m0 = blockIdx.y * 64;
    int n0 = blockIdx.x * 64;
    int lm = tid >> 2;
    int lk = (tid & 3) * 4;
    float acc[4][4] = {};
    const float* pA = A + (size_t)(m0 + lm) * K + lk;
    int nrow = n0 + lm;
    const float* pW = W + (size_t)nrow * K + lk;
    bool wvalid = (nrow < N);
    for (int k0 = 0; k0 < K; k0 += 16) {
        float4 a = *(const float4*)(pA + k0);
        float4 w = wvalid ? *(const float4*)(pW + k0) : make_float4(0.f, 0.f, 0.f, 0.f);
        As[lk + 0][lm] = a.x; As[lk + 1][lm] = a.y; As[lk + 2][lm] = a.z; As[lk + 3][lm] = a.w;
        Bs[lk + 0][lm] = w.x; Bs[lk + 1][lm] = w.y; Bs[lk + 2][lm] = w.z; Bs[lk + 3][lm] = w.w;
        __syncthreads();
#pragma unroll
        for (int kk = 0; kk < 16; kk++) {
            float4 av = *(const float4*)&As[kk][tr * 4];
            float4 bv = *(const float4*)&Bs[kk][tc * 4];
            float aa[4] = {av.x, av.y, av.z, av.w};
            float bb[4] = {bv.x, bv.y, bv.z, bv.w};
#pragma unroll
            for (int i = 0; i < 4; i++)
#pragma unroll
                for (int j = 0; j < 4; j++)
                    acc[i][j] = fmaf(aa[i], bb[j], acc[i][j]);
        }
        __syncthreads();
    }
#pragma unroll
    for (int i = 0; i < 4; i++) {
        int m = m0 + tr * 4 + i;
#pragma unroll
        for (int j = 0; j < 4; j++) {
            int n = n0 + tc * 4 + j;
            if (n < N) C[(size_t)m * N + n] = acc[i][j];
        }
    }
}

__global__ __launch_bounds__(256) void k_gemm_xz(const float* __restrict__ Win) {
    gemm_body(g_h, Win, g_xz, E2z, Dz);
}
__global__ __launch_bounds__(256) void k_gemm_xdb(const float* __restrict__ Wxp) {
    gemm_body(g_x, Wxp, g_xdb, XDBz, DIz);
}
__global__ __launch_bounds__(256) void k_gemm_out(const float* __restrict__ Wout, float* __restrict__ out) {
    gemm_body(g_y, Wout, out, Dz, DIz);
}

// ============================================================================
// Kernel: depthwise causal conv (4 taps) + bias + SiLU  -> g_x
// ============================================================================
__global__ __launch_bounds__(256) void k_conv(
    const float* __restrict__ cw, const float* __restrict__ cb)
{
    int idx = blockIdx.x * blockDim.x + threadIdx.x;   // r*DI + d
    if (idx >= BLz * DIz) return;
    int r = idx / DIz, d = idx - r * DIz;
    int t = r & (Lz - 1);
    // hoist weights/bias
    float w0 = cw[d * 4 + 0], w1 = cw[d * 4 + 1], w2 = cw[d * 4 + 2], w3 = cw[d * 4 + 3];
    float s = cb[d];
    const float* base = g_xz + (size_t)r * E2z + d;
    float x3 = base[0];                                  // tap j=3 (current t)
    float x2 = (t >= 1) ? base[-(ptrdiff_t)E2z]     : 0.f;
    float x1 = (t >= 2) ? base[-(ptrdiff_t)(2*E2z)] : 0.f;
    float x0 = (t >= 3) ? base[-(ptrdiff_t)(3*E2z)] : 0.f;
    s = fmaf(w0, x0, s);
    s = fmaf(w1, x1, s);
    s = fmaf(w2, x2, s);
    s = fmaf(w3, x3, s);
    float sig = 1.f / (1.f + __expf(-s));
    g_x[idx] = s * sig;
}

// ============================================================================
// Kernel: dt = softplus(xdb[:, :12] @ W_dt^T + b_dt) ; dtu = dt * u
// ============================================================================
__global__ __launch_bounds__(256) void k_dtprep(
    const float* __restrict__ Wdt, const float* __restrict__ bdt)
{
    int idx = blockIdx.x * blockDim.x + threadIdx.x;   // r*DI + d
    if (idx >= BLz * DIz) return;
    int r = idx / DIz, d = idx - r * DIz;
    const float* xb = g_xdb + (size_t)r * XDBz;
    const float* wr = Wdt + d * 12;
    float s = bdt[d];
#pragma unroll
    for (int j = 0; j < 12; j++) s = fmaf(xb[j], wr[j], s);
    // stable softplus
    float sp;
    if (s > 20.f)       sp = s;
    else                sp = log1pf(__expf(s));
    g_dt[idx] = sp;
    g_dtu[idx] = sp * g_x[idx];
}

// ============================================================================
// Kernel: selective scan. warp = one (b,d) channel; lane holds states n=lane,
// n=lane+32 (C folded into B so y is a pure lane-sum). Chunked smem staging of
// B*C (shared by the 4 d-channels of the block), dt, dt*u.
// Fused epilogue: y = (scan + x*D_skip) * silu(z) -> g_y
// ============================================================================
#define TCH 64
__global__ __launch_bounds__(128) void k_scan(
    const float* __restrict__ Alog, const float* __restrict__ Cf,
    const float* __restrict__ Dsk)
{
    __shared__ float2 sBC[TCH][32];
    __shared__ float2 sDD[4][TCH];
    __shared__ float  sY[4][TCH];

    int b    = blockIdx.x / (DIz / 4);
    int dblk = blockIdx.x % (DIz / 4);
    int tid = threadIdx.x, lane = tid & 31, wid = tid >> 5;
    int d = dblk * 4 + wid;

    const float LOG2E = 1.4426950408889634f;
    float aa0 = -expf(Alog[d * DSz + lane])      * LOG2E;  // A*log2e (A<0)
    float aa1 = -expf(Alog[d * DSz + lane + 32]) * LOG2E;
    float h0 = 0.f, h1 = 0.f;
    int rbase = b * Lz;

    for (int c = 0; c < Lz / TCH; c++) {
        int r0 = rbase + c * TCH;
        // stage B*C tile  (64 t x 64 n), layout: [t][lane] = (n=lane, n=lane+32)
        for (int i = tid; i < TCH * DSz; i += 128) {
            int t = i >> 6, n = i & 63;
            float v = g_xdb[(size_t)(r0 + t) * XDBz + DRz + n] * Cf[n];
            ((float*)&sBC[t][0])[(n & 31) * 2 + (n >> 5)] = v;
        }
        // stage (dt, dt*u) per d-channel
        for (int i = tid; i < 4 * TCH; i += 128) {
            int dl = i >> 6, t = i & 63;
            size_t rr = (size_t)(r0 + t) * DIz + dblk * 4 + dl;
            sDD[dl][t] = make_float2(g_dt[rr], g_dtu[rr]);
        }
        __syncthreads();

#pragma unroll 4
        for (int t = 0; t < TCH; t++) {
            float2 dd = sDD[wid][t];      // uniform broadcast within warp
            float2 bc = sBC[t][lane];
            float dA0 = exp2f(dd.x * aa0);
            float dA1 = exp2f(dd.x * aa1);
            h0 = fmaf(dA0, h0, dd.y * bc.x);
            h1 = fmaf(dA1, h1, dd.y * bc.y);
            float p = h0 + h1;
#pragma unroll
            for (int o = 16; o; o >>= 1) p += __shfl_xor_sync(0xffffffffu, p, o);
            if (lane == 0) sY[wid][t] = p;
        }
        __syncthreads();

        // fused epilogue: y = (scan + x*D_skip)*silu(z)
        for (int i = tid; i < 4 * TCH; i += 128) {
            int dl = i >> 6, t = i & 63;
            int rr = r0 + t;
            int dg = dblk * 4 + dl;
            float xv = g_x[(size_t)rr * DIz + dg];
            float zv = g_xz[(size_t)rr * E2z + DIz + dg];
            float y = sY[dl][t] + xv * Dsk[dg];
            float sig = 1.f / (1.f + __expf(-zv));
            g_y[(size_t)rr * DIz + dg] = y * (zv * sig);
        }
        __syncthreads();
    }
}

// ============================================================================
// launcher
// ============================================================================
extern "C" void kernel_launch(void* const* d_in, const int* in_sizes, int n_in,
                              void* d_out, int out_size)
{
    (void)in_sizes; (void)n_in; (void)out_size;
    const float* hs   = (const float*)d_in[0];
    const float* res  = (const float*)d_in[1];
    const float* lw   = (const float*)d_in[2];
    const float* lb   = (const float*)d_in[3];
    const float* Win  = (const float*)d_in[4];
    const float* cw   = (const float*)d_in[5];
    const float* cb   = (const float*)d_in[6];
    const float* Wxp  = (const float*)d_in[7];
    const float* Wdt  = (const float*)d_in[8];
    const float* bdt  = (const float*)d_in[9];
    const float* Alog = (const float*)d_in[10];
    const float* Dsk  = (const float*)d_in[11];
    const float* Cf   = (const float*)d_in[12];
    const float* Wout = (const float*)d_in[13];
    float* out = (float*)d_out;
    float* out_res = out + (size_t)BLz * Dz;

    // 1. residual + LN
    k_ln<<<BLz / 8, 256>>>(hs, res, lw, lb, out_res);
    // 2. xz = h @ W_in^T   [8192 x 768]
    { dim3 g(E2z / 64, BLz / 64); k_gemm_xz<<<g, 256>>>(Win); }
    // 3. causal depthwise conv + SiLU
    k_conv<<<(BLz * DIz) / 256, 256>>>(cw, cb);
    // 4. xdb = x @ W_xproj^T   [8192 x 76]
    { dim3 g((XDBz + 63) / 64, BLz / 64); k_gemm_xdb<<<g, 256>>>(Wxp); }
    // 5. dt prep
    k_dtprep<<<(BLz * DIz) / 256, 256>>>(Wdt, bdt);
    // 6. selective scan + gate fusion
    k_scan<<<Bz * (DIz / 4), 128>>>(Alog, Cf, Dsk);
    // 7. out = y @ W_out^T
    { dim3 g(Dz / 64, BLz / 64); k_gemm_out<<<g, 256>>>(Wout, out);
    }
}